// round 14
// baseline (speedup 1.0000x reference)
#include <cuda_runtime.h>
#include <cuda_fp16.h>
#include <cstdint>
#include <math.h>

#define Bsz 64
#define Tt  512
#define Din 256
#define Hs  1024
#define G4  4096
#define MROWS (Tt*Bsz)
#define NBLK_REC 128
#define WSROW 1032
#define GS 3
#define GSTRIDE 40
#define STAGEH (128*GSTRIDE)
#define RTHREADS 384
#define SETH2 (64*17)           // half2 per smem partial set
// smem sets: 0-3 = Whh0 ksl0-3 | 4-5 = Whh1 ksl0-1

// persistent scratch
__device__ __half g_xgh[(size_t)MROWS * G4];     // [T][B][4H] gate-major layer-0 input gates
__device__ __half g_h0buf[2][Bsz * Hs];          // layer-0 hidden (physpos layout)
__device__ __half g_h1buf[2][Bsz * Hs];          // layer-1 hidden (physpos layout)
__device__ __half g_r1p[(size_t)2 * NBLK_REC * 4 * 64 * 32];  // Wih1 partials (parity ring)
__device__ __half g_xh[(size_t)Bsz * Tt * Din];
__device__ __half g_w0h[(size_t)G4 * Din];
__device__ unsigned g_barcnt;
__device__ unsigned g_bargen;

// ---------------------------------------------------------------- helpers
__device__ __forceinline__ void mma_f16(float* d, const unsigned* a, unsigned b0, unsigned b1) {
    asm volatile(
        "mma.sync.aligned.m16n8k16.row.col.f32.f16.f16.f32 "
        "{%0,%1,%2,%3},{%4,%5,%6,%7},{%8,%9},{%0,%1,%2,%3};"
        : "+f"(d[0]), "+f"(d[1]), "+f"(d[2]), "+f"(d[3])
        : "r"(a[0]), "r"(a[1]), "r"(a[2]), "r"(a[3]), "r"(b0), "r"(b1));
}

__device__ __forceinline__ void cp16(unsigned saddr, const void* g) {
    asm volatile("cp.async.cg.shared.global [%0], [%1], 16;" :: "r"(saddr), "l"(g));
}

__device__ __forceinline__ int perm16(int c) {
    return (c < 8) ? ((c >> 1) * 4 + (c & 1)) : (((c - 8) >> 1) * 4 + 2 + (c & 1));
}
__device__ __forceinline__ int physpos(int u) {
    int blk = u >> 4;
    int o = perm16(u & 15);
    int tg = o >> 2, inner = o & 3;
    return (blk >> 1) * 32 + tg * 8 + (blk & 1) * 4 + inner;
}

__device__ __forceinline__ float sigf(float x)  { return __fdividef(1.f, 1.f + __expf(-x)); }
__device__ __forceinline__ float tanhf_(float x){ return __fdividef(2.f, 1.f + __expf(-2.f * x)) - 1.f; }

// best-found barrier (r8): CTA arrival by tid0, per-warp release observation.
__device__ __forceinline__ void grid_barrier(unsigned nblk, unsigned expect) {
    __syncthreads();
    if (threadIdx.x == 0) {
        asm volatile("fence.acq_rel.gpu;" ::: "memory");
        if (atomicAdd(&g_barcnt, 1u) == nblk - 1u) {
            g_barcnt = 0;
            asm volatile("st.release.gpu.global.u32 [%0], %1;" :: "l"(&g_bargen), "r"(expect) : "memory");
        }
    }
    if ((threadIdx.x & 31) == 0) {
        unsigned cur;
        do {
            asm volatile("ld.acquire.gpu.global.u32 %0, [%1];" : "=r"(cur) : "l"(&g_bargen) : "memory");
        } while (cur < expect);
    }
    __syncwarp();
}

// ---------------------------------------------------------------- fp32 -> fp16 (+barrier reset)
__global__ void tohalf_kernel(const float* __restrict__ src, __half* __restrict__ dst, int n)
{
    if (blockIdx.x == 0 && threadIdx.x == 0) { g_barcnt = 0; g_bargen = 0; }
    for (int i = blockIdx.x * blockDim.x + threadIdx.x; i < n; i += gridDim.x * blockDim.x)
        dst[i] = __float2half_rn(src[i]);
}

// ---------------------------------------------------------------- xg0 GEMM (unchanged)
#define GSMEM (GS * STAGEH * 2 * 2)

__global__ __launch_bounds__(256, 2)
void gemm_xg_kernel(const __half* __restrict__ A, const __half* __restrict__ W,
                    const float* __restrict__ bias, int K)
{
    extern __shared__ __half gsm[];
    __half* As = gsm;
    __half* Bs = gsm + GS * STAGEH;

    const int tid  = threadIdx.x;
    const int lane = tid & 31, warp = tid >> 5;
    const int gid  = lane >> 2, tig = lane & 3;
    const int wm   = warp >> 1, wn = warp & 1;
    const int bm   = blockIdx.y * 128, bn = blockIdx.x * 128;

    const __half* ga[2]; const __half* gb[2]; int soff[2];
    #pragma unroll
    for (int j = 0; j < 2; ++j) {
        int i = tid + j * 256;
        int row = i >> 2, seg = (i & 3) * 8;
        int rm = bm + row;
        ga[j] = A + ((size_t)(rm & 63) * Tt + (rm >> 6)) * Din + seg;
        gb[j] = W + (size_t)(bn + row) * K + seg;
        soff[j] = row * GSTRIDE + seg;
    }
    unsigned sA = (unsigned)__cvta_generic_to_shared(As);
    unsigned sB = (unsigned)__cvta_generic_to_shared(Bs);

    const int nch = K / 32;

    auto stage = [&](int s, int k0) {
        #pragma unroll
        for (int j = 0; j < 2; ++j) {
            cp16(sA + (s * STAGEH + soff[j]) * 2, ga[j] + k0);
            cp16(sB + (s * STAGEH + soff[j]) * 2, gb[j] + k0);
        }
        asm volatile("cp.async.commit_group;");
    };

    stage(0, 0);
    stage(1, 32);

    float acc[2][8][4] = {};

    for (int c = 0; c < nch; ++c) {
        if (c + 1 < nch) asm volatile("cp.async.wait_group 1;");
        else             asm volatile("cp.async.wait_group 0;");
        __syncthreads();
        if (c + 2 < nch) stage((c + 2) % GS, (c + 2) * 32);

        const __half* Asl = As + (c % GS) * STAGEH;
        const __half* Bsl = Bs + (c % GS) * STAGEH;
        #pragma unroll
        for (int s = 0; s < 2; ++s) {
            int kk = s * 16;
            unsigned a[2][4];
            #pragma unroll
            for (int mt = 0; mt < 2; ++mt) {
                int m = wm * 32 + mt * 16 + gid;
                a[mt][0] = *(const unsigned*)&Asl[m * GSTRIDE + kk + 2 * tig];
                a[mt][1] = *(const unsigned*)&Asl[(m + 8) * GSTRIDE + kk + 2 * tig];
                a[mt][2] = *(const unsigned*)&Asl[m * GSTRIDE + kk + 8 + 2 * tig];
                a[mt][3] = *(const unsigned*)&Asl[(m + 8) * GSTRIDE + kk + 8 + 2 * tig];
            }
            #pragma unroll
            for (int nt = 0; nt < 8; ++nt) {
                int n = wn * 64 + nt * 8 + gid;
                unsigned b0 = *(const unsigned*)&Bsl[n * GSTRIDE + kk + 2 * tig];
                unsigned b1 = *(const unsigned*)&Bsl[n * GSTRIDE + kk + 8 + 2 * tig];
                mma_f16(acc[0][nt], a[0], b0, b1);
                mma_f16(acc[1][nt], a[1], b0, b1);
            }
        }
    }

    #pragma unroll
    for (int mt = 0; mt < 2; ++mt) {
        #pragma unroll
        for (int nt = 0; nt < 8; ++nt) {
            int row = bm + wm * 32 + mt * 16 + gid;
            int col = bn + wn * 64 + nt * 8 + 2 * tig;
            float bc0 = bias[col], bc1 = bias[col + 1];
            *reinterpret_cast<__half2*>(&g_xgh[(size_t)row * G4 + col]) =
                __floats2half2_rn(acc[mt][nt][0] + bc0, acc[mt][nt][1] + bc1);
            *reinterpret_cast<__half2*>(&g_xgh[(size_t)(row + 8) * G4 + col]) =
                __floats2half2_rn(acc[mt][nt][2] + bc0, acc[mt][nt][3] + bc1);
        }
    }
}

// ---------------------------------------------------------------- fused 2-layer recurrence
// SG-A (warps 0-7, K4xM2): Whh0 + Wih1 on SHARED h0 fragments (h0 read once).
// Whh0 partials -> smem sets 0-3; Wih1 partials -> global parity ring (consumed
// next step by SG-B; ordered by grid barrier). SG-B (warps 8-11, K2xM2): Whh1 as r13,
// + prefetched Wih1 partials + bias -> h1. Bars: 1 = SG-A (256 thr), 2 = SG-B (128 thr).
#define RSMEM (96*WSROW*2 + 6*SETH2*4)

__global__ __launch_bounds__(RTHREADS, 1)
void rec2_kernel(const float* __restrict__ Whh0, const float* __restrict__ Wih1,
                 const float* __restrict__ Whh1, const float* __restrict__ b1)
{
    extern __shared__ unsigned char smraw[];
    __half*  Ws   = (__half*)smraw;                        // [3][32][WSROW]
    __half2* scr2 = (__half2*)(smraw + 96 * WSROW * 2);    // [6][64][17]

    const int tid  = threadIdx.x;
    const int lane = tid & 31, warp = tid >> 5;
    const int gid  = lane >> 2, tig = lane & 3;
    const bool sgA = warp < 8;
    const int u0   = blockIdx.x * 8;

    // SG-A coords
    const int kslA = warp >> 1, msA = warp & 1;      // (valid when sgA)
    const int rEA  = warp * 8 + gid;                 // epilogue row (SG-A)
    // SG-B coords
    const int wb   = warp - 8;
    const int kslB = wb >> 1, msB = wb & 1;
    const int rEb  = wb * 16 + gid;                  // epilogue rows rEb, rEb+8

    // one-time: 3 weight slices -> smem fp16 (rows l = g*8+n)
    {
        const float* srcs[3] = {Whh0, Wih1, Whh1};
        for (int sl = 0; sl < 3; ++sl) {
            const float* src = srcs[sl];
            __half* dst = Ws + sl * 32 * WSROW;
            for (int i = tid; i < 32 * Hs; i += RTHREADS) {
                int l = i >> 10, k = i & 1023;
                int g = l >> 3, n = l & 7;
                dst[l * WSROW + k] = __float2half_rn(src[(size_t)(g * Hs + u0 + n) * Hs + k]);
            }
        }
    }
    // zero h[-1] buffers: h0[-1] parity 1 (read s=0), h1[-1] parity 1 (read s=2)
    for (int i = tid; i < 512; i += RTHREADS) {
        int b = i >> 3, uu = i & 7;
        int col = physpos(u0 + uu);
        g_h0buf[1][b * Hs + col] = __float2half_rn(0.f);
        g_h1buf[1][b * Hs + col] = __float2half_rn(0.f);
    }

    // ldmatrix lane pointers
    const int ltile = lane >> 3, lrow = lane & 7;
    unsigned lpW0a, lpW0b, lpW1a, lpW1b, lpB0, lpB1;
    {
        int ro0 = ((ltile >> 1)) * 8 + lrow;         // gates 0-1 rows
        int ro1 = (2 + (ltile >> 1)) * 8 + lrow;     // gates 2-3 rows
        int ko  = (ltile & 1) * 8;
        const __half* w0 = Ws + 0 * 32 * WSROW + (sgA ? kslA * 256 : 0);
        const __half* w1 = Ws + 1 * 32 * WSROW + (sgA ? kslA * 256 : 0);
        const __half* w2 = Ws + 2 * 32 * WSROW + (sgA ? 0 : kslB * 512);
        lpW0a = (unsigned)__cvta_generic_to_shared(w0 + (size_t)ro0 * WSROW + ko);
        lpW0b = (unsigned)__cvta_generic_to_shared(w0 + (size_t)ro1 * WSROW + ko);
        lpW1a = (unsigned)__cvta_generic_to_shared(w1 + (size_t)ro0 * WSROW + ko);
        lpW1b = (unsigned)__cvta_generic_to_shared(w1 + (size_t)ro1 * WSROW + ko);
        lpB0  = (unsigned)__cvta_generic_to_shared(w2 + (size_t)ro0 * WSROW + ko);
        lpB1  = (unsigned)__cvta_generic_to_shared(w2 + (size_t)ro1 * WSROW + ko);
    }

    float cst[4] = {0.f, 0.f, 0.f, 0.f};
    float bi1[4][2];
    if (!sgA) {
        #pragma unroll
        for (int g = 0; g < 4; ++g) {
            bi1[g][0] = b1[g * Hs + u0 + 2 * tig];
            bi1[g][1] = b1[g * Hs + u0 + 2 * tig + 1];
        }
    }
    const int wpos = physpos(u0 + 2 * tig);

    unsigned ep = 0;
    grid_barrier(NBLK_REC, ++ep);

    // SG-A@s (s<=Tt): h0[s-1] -> {Whh0 partials -> h0[s] (s<Tt)} + {Wih1 partials -> ring[s&1]}
    // SG-B@s (s>=2):  Whh1@h1[s-3 parity] + ring[(s-1)&1] + b1 -> h1[s-2] (parity s&1)
    for (int s = 0; s <= Tt + 1; ++s) {
        if (sgA) {
            if (s <= Tt) {
                __half2 px[4];
                if (s < Tt) {
                    const __half* xb = g_xgh + ((size_t)s * Bsz + rEA) * G4 + u0 + 2 * tig;
                    #pragma unroll
                    for (int g = 0; g < 4; ++g)
                        px[g] = *(const __half2*)(xb + g * Hs);
                }

                float aW0[4][2][4] = {}, aW1[4][2][4] = {};
                const __half* hp = g_h0buf[(s + 1) & 1];
                const int r0 = msA * 32 + gid;
                const uint4* aP0 = (const uint4*)(hp + (size_t)r0 * Hs + kslA * 256) + tig;
                const uint4* aP1 = (const uint4*)(hp + (size_t)(r0 + 8) * Hs + kslA * 256) + tig;
                const uint4* aP2 = (const uint4*)(hp + (size_t)(r0 + 16) * Hs + kslA * 256) + tig;
                const uint4* aP3 = (const uint4*)(hp + (size_t)(r0 + 24) * Hs + kslA * 256) + tig;

                #pragma unroll
                for (int j = 0; j < 8; ++j) {
                    uint4 v0 = aP0[4 * j], v1 = aP1[4 * j], v2 = aP2[4 * j], v3 = aP3[4 * j];
                    unsigned b0, b1r, b2, b3;
                    {
                        unsigned a0[4] = {v0.x, v1.x, v0.y, v1.y};
                        unsigned a1[4] = {v2.x, v3.x, v2.y, v3.y};
                        asm volatile("ldmatrix.sync.aligned.m8n8.x4.shared.b16 {%0,%1,%2,%3}, [%4];"
                                     : "=r"(b0), "=r"(b1r), "=r"(b2), "=r"(b3) : "r"(lpW0a + j * 64));
                        mma_f16(aW0[0][0], a0, b0, b1r); mma_f16(aW0[0][1], a1, b0, b1r);
                        mma_f16(aW0[1][0], a0, b2, b3);  mma_f16(aW0[1][1], a1, b2, b3);
                        asm volatile("ldmatrix.sync.aligned.m8n8.x4.shared.b16 {%0,%1,%2,%3}, [%4];"
                                     : "=r"(b0), "=r"(b1r), "=r"(b2), "=r"(b3) : "r"(lpW0b + j * 64));
                        mma_f16(aW0[2][0], a0, b0, b1r); mma_f16(aW0[2][1], a1, b0, b1r);
                        mma_f16(aW0[3][0], a0, b2, b3);  mma_f16(aW0[3][1], a1, b2, b3);
                        asm volatile("ldmatrix.sync.aligned.m8n8.x4.shared.b16 {%0,%1,%2,%3}, [%4];"
                                     : "=r"(b0), "=r"(b1r), "=r"(b2), "=r"(b3) : "r"(lpW1a + j * 64));
                        mma_f16(aW1[0][0], a0, b0, b1r); mma_f16(aW1[0][1], a1, b0, b1r);
                        mma_f16(aW1[1][0], a0, b2, b3);  mma_f16(aW1[1][1], a1, b2, b3);
                        asm volatile("ldmatrix.sync.aligned.m8n8.x4.shared.b16 {%0,%1,%2,%3}, [%4];"
                                     : "=r"(b0), "=r"(b1r), "=r"(b2), "=r"(b3) : "r"(lpW1b + j * 64));
                        mma_f16(aW1[2][0], a0, b0, b1r); mma_f16(aW1[2][1], a1, b0, b1r);
                        mma_f16(aW1[3][0], a0, b2, b3);  mma_f16(aW1[3][1], a1, b2, b3);
                    }
                    {
                        unsigned a0[4] = {v0.z, v1.z, v0.w, v1.w};
                        unsigned a1[4] = {v2.z, v3.z, v2.w, v3.w};
                        asm volatile("ldmatrix.sync.aligned.m8n8.x4.shared.b16 {%0,%1,%2,%3}, [%4];"
                                     : "=r"(b0), "=r"(b1r), "=r"(b2), "=r"(b3) : "r"(lpW0a + j * 64 + 32));
                        mma_f16(aW0[0][0], a0, b0, b1r); mma_f16(aW0[0][1], a1, b0, b1r);
                        mma_f16(aW0[1][0], a0, b2, b3);  mma_f16(aW0[1][1], a1, b2, b3);
                        asm volatile("ldmatrix.sync.aligned.m8n8.x4.shared.b16 {%0,%1,%2,%3}, [%4];"
                                     : "=r"(b0), "=r"(b1r), "=r"(b2), "=r"(b3) : "r"(lpW0b + j * 64 + 32));
                        mma_f16(aW0[2][0], a0, b0, b1r); mma_f16(aW0[2][1], a1, b0, b1r);
                        mma_f16(aW0[3][0], a0, b2, b3);  mma_f16(aW0[3][1], a1, b2, b3);
                        asm volatile("ldmatrix.sync.aligned.m8n8.x4.shared.b16 {%0,%1,%2,%3}, [%4];"
                                     : "=r"(b0), "=r"(b1r), "=r"(b2), "=r"(b3) : "r"(lpW1a + j * 64 + 32));
                        mma_f16(aW1[0][0], a0, b0, b1r); mma_f16(aW1[0][1], a1, b0, b1r);
                        mma_f16(aW1[1][0], a0, b2, b3);  mma_f16(aW1[1][1], a1, b2, b3);
                        asm volatile("ldmatrix.sync.aligned.m8n8.x4.shared.b16 {%0,%1,%2,%3}, [%4];"
                                     : "=r"(b0), "=r"(b1r), "=r"(b2), "=r"(b3) : "r"(lpW1b + j * 64 + 32));
                        mma_f16(aW1[2][0], a0, b0, b1r); mma_f16(aW1[2][1], a1, b0, b1r);
                        mma_f16(aW1[3][0], a0, b2, b3);  mma_f16(aW1[3][1], a1, b2, b3);
                    }
                }

                // Whh0 partials -> smem set kslA
                {
                    __half2* sc = scr2 + kslA * SETH2;
                    #pragma unroll
                    for (int g = 0; g < 4; ++g)
                        #pragma unroll
                        for (int mt = 0; mt < 2; ++mt) {
                            int row = r0 + mt * 16;
                            sc[row * 17 + g * 4 + tig]       = __floats2half2_rn(aW0[g][mt][0], aW0[g][mt][1]);
                            sc[(row + 8) * 17 + g * 4 + tig] = __floats2half2_rn(aW0[g][mt][2], aW0[g][mt][3]);
                        }
                }
                // Wih1 partials -> global ring, parity s&1 (uint4 = 4 gates)
                {
                    __half* gp = g_r1p + ((size_t)((s & 1) * NBLK_REC + blockIdx.x) * 4 + kslA) * 2048;
                    #pragma unroll
                    for (int mt = 0; mt < 2; ++mt) {
                        int row = r0 + mt * 16;
                        uint4 u; __half2 t;
                        t = __floats2half2_rn(aW1[0][mt][0], aW1[0][mt][1]); u.x = *(unsigned*)&t;
                        t = __floats2half2_rn(aW1[1][mt][0], aW1[1][mt][1]); u.y = *(unsigned*)&t;
                        t = __floats2half2_rn(aW1[2][mt][0], aW1[2][mt][1]); u.z = *(unsigned*)&t;
                        t = __floats2half2_rn(aW1[3][mt][0], aW1[3][mt][1]); u.w = *(unsigned*)&t;
                        *(uint4*)(gp + (size_t)row * 32 + tig * 8) = u;
                        t = __floats2half2_rn(aW1[0][mt][2], aW1[0][mt][3]); u.x = *(unsigned*)&t;
                        t = __floats2half2_rn(aW1[1][mt][2], aW1[1][mt][3]); u.y = *(unsigned*)&t;
                        t = __floats2half2_rn(aW1[2][mt][2], aW1[2][mt][3]); u.z = *(unsigned*)&t;
                        t = __floats2half2_rn(aW1[3][mt][2], aW1[3][mt][3]); u.w = *(unsigned*)&t;
                        *(uint4*)(gp + (size_t)(row + 8) * 32 + tig * 8) = u;
                    }
                }

                asm volatile("bar.sync 1, 256;" ::: "memory");

                if (s < Tt) {
                    float2 G[4];
                    #pragma unroll
                    for (int g = 0; g < 4; ++g) {
                        float gx = 0.f, gy = 0.f;
                        #pragma unroll
                        for (int k = 0; k < 4; ++k) {
                            __half2 p = scr2[k * SETH2 + rEA * 17 + g * 4 + tig];
                            gx += __low2float(p); gy += __high2float(p);
                        }
                        G[g] = make_float2(gx, gy);
                    }
                    __half* hn = g_h0buf[s & 1];
                    float hv[2];
                    #pragma unroll
                    for (int fc = 0; fc < 2; ++fc) {
                        float gi = (fc ? G[0].y : G[0].x) + (fc ? __high2float(px[0]) : __low2float(px[0]));
                        float gf = (fc ? G[1].y : G[1].x) + (fc ? __high2float(px[1]) : __low2float(px[1]));
                        float gg = (fc ? G[2].y : G[2].x) + (fc ? __high2float(px[2]) : __low2float(px[2]));
                        float go = (fc ? G[3].y : G[3].x) + (fc ? __high2float(px[3]) : __low2float(px[3]));
                        gi = sigf(gi); gf = sigf(gf); gg = tanhf_(gg); go = sigf(go);
                        float c = gf * cst[fc] + gi * gg;
                        cst[fc] = c;
                        hv[fc] = go * tanhf_(c);
                    }
                    *reinterpret_cast<__half2*>(hn + (size_t)rEA * Hs + wpos) = __floats2half2_rn(hv[0], hv[1]);
                }
            }
        } else {
            if (s >= 2) {
                // prefetch Wih1 partials from ring parity (s-1)&1 (hidden under MMA)
                uint4 pw[4][2];
                {
                    const __half* gpr = g_r1p + (size_t)(((s - 1) & 1) * NBLK_REC + blockIdx.x) * 4 * 2048;
                    #pragma unroll
                    for (int k = 0; k < 4; ++k) {
                        pw[k][0] = *(const uint4*)(gpr + (size_t)k * 2048 + rEb * 32 + tig * 8);
                        pw[k][1] = *(const uint4*)(gpr + (size_t)k * 2048 + (rEb + 8) * 32 + tig * 8);
                    }
                }

                float acc[4][2][4] = {};
                const __half* hp = g_h1buf[(s + 1) & 1];
                const int r0 = msB * 32 + gid;
                const uint4* aP0 = (const uint4*)(hp + (size_t)r0 * Hs + kslB * 512) + tig;
                const uint4* aP1 = (const uint4*)(hp + (size_t)(r0 + 8) * Hs + kslB * 512) + tig;
                const uint4* aP2 = (const uint4*)(hp + (size_t)(r0 + 16) * Hs + kslB * 512) + tig;
                const uint4* aP3 = (const uint4*)(hp + (size_t)(r0 + 24) * Hs + kslB * 512) + tig;
                #pragma unroll 8
                for (int j = 0; j < 16; ++j) {
                    uint4 v0 = aP0[4 * j], v1 = aP1[4 * j], v2 = aP2[4 * j], v3 = aP3[4 * j];
                    unsigned b0, b1r, b2, b3;
                    {
                        unsigned a0[4] = {v0.x, v1.x, v0.y, v1.y};
                        unsigned a1[4] = {v2.x, v3.x, v2.y, v3.y};
                        asm volatile("ldmatrix.sync.aligned.m8n8.x4.shared.b16 {%0,%1,%2,%3}, [%4];"
                                     : "=r"(b0), "=r"(b1r), "=r"(b2), "=r"(b3) : "r"(lpB0 + j * 64));
                        mma_f16(acc[0][0], a0, b0, b1r); mma_f16(acc[0][1], a1, b0, b1r);
                        mma_f16(acc[1][0], a0, b2, b3);  mma_f16(acc[1][1], a1, b2, b3);
                        asm volatile("ldmatrix.sync.aligned.m8n8.x4.shared.b16 {%0,%1,%2,%3}, [%4];"
                                     : "=r"(b0), "=r"(b1r), "=r"(b2), "=r"(b3) : "r"(lpB1 + j * 64));
                        mma_f16(acc[2][0], a0, b0, b1r); mma_f16(acc[2][1], a1, b0, b1r);
                        mma_f16(acc[3][0], a0, b2, b3);  mma_f16(acc[3][1], a1, b2, b3);
                    }
                    {
                        unsigned a0[4] = {v0.z, v1.z, v0.w, v1.w};
                        unsigned a1[4] = {v2.z, v3.z, v2.w, v3.w};
                        asm volatile("ldmatrix.sync.aligned.m8n8.x4.shared.b16 {%0,%1,%2,%3}, [%4];"
                                     : "=r"(b0), "=r"(b1r), "=r"(b2), "=r"(b3) : "r"(lpB0 + j * 64 + 32));
                        mma_f16(acc[0][0], a0, b0, b1r); mma_f16(acc[0][1], a1, b0, b1r);
                        mma_f16(acc[1][0], a0, b2, b3);  mma_f16(acc[1][1], a1, b2, b3);
                        asm volatile("ldmatrix.sync.aligned.m8n8.x4.shared.b16 {%0,%1,%2,%3}, [%4];"
                                     : "=r"(b0), "=r"(b1r), "=r"(b2), "=r"(b3) : "r"(lpB1 + j * 64 + 32));
                        mma_f16(acc[2][0], a0, b0, b1r); mma_f16(acc[2][1], a1, b0, b1r);
                        mma_f16(acc[3][0], a0, b2, b3);  mma_f16(acc[3][1], a1, b2, b3);
                    }
                }

                // Whh1 partials -> smem set 4 + kslB
                {
                    __half2* sc = scr2 + (4 + kslB) * SETH2;
                    #pragma unroll
                    for (int g = 0; g < 4; ++g)
                        #pragma unroll
                        for (int mt = 0; mt < 2; ++mt) {
                            int row = r0 + mt * 16;
                            sc[row * 17 + g * 4 + tig]       = __floats2half2_rn(acc[g][mt][0], acc[g][mt][1]);
                            sc[(row + 8) * 17 + g * 4 + tig] = __floats2half2_rn(acc[g][mt][2], acc[g][mt][3]);
                        }
                }

                asm volatile("bar.sync 2, 128;" ::: "memory");

                // epilogue: sum Whh1 (2 smem sets) + Wih1 (4 global sets) + bias
                float2 G[4][2];
                #pragma unroll
                for (int g = 0; g < 4; ++g) {
                    #pragma unroll
                    for (int fr = 0; fr < 2; ++fr) {
                        int r = rEb + fr * 8;
                        __half2 pa = scr2[4 * SETH2 + r * 17 + g * 4 + tig];
                        __half2 pb = scr2[5 * SETH2 + r * 17 + g * 4 + tig];
                        float gx = __low2float(pa) + __low2float(pb);
                        float gy = __high2float(pa) + __high2float(pb);
                        #pragma unroll
                        for (int k = 0; k < 4; ++k) {
                            unsigned c = (g == 0) ? pw[k][fr].x : (g == 1) ? pw[k][fr].y
                                       : (g == 2) ? pw[k][fr].z : pw[k][fr].w;
                            __half2 v = *reinterpret_cast<__half2*>(&c);
                            gx += __low2float(v); gy += __high2float(v);
                        }
                        G[g][fr] = make_float2(gx, gy);
                    }
                }
                __half* hn = g_h1buf[s & 1];
                float hv[4];
                #pragma unroll
                for (int j = 0; j < 4; ++j) {
                    int fr = j >> 1, fc = j & 1;
                    float gi = (fc ? G[0][fr].y : G[0][fr].x) + bi1[0][fc];
                    float gf = (fc ? G[1][fr].y : G[1][fr].x) + bi1[1][fc];
                    float gg = (fc ? G[2][fr].y : G[2][fr].x) + bi1[2][fc];
                    float go = (fc ? G[3][fr].y : G[3][fr].x) + bi1[3][fc];
                    gi = sigf(gi); gf = sigf(gf); gg = tanhf_(gg); go = sigf(go);
                    float c = gf * cst[j] + gi * gg;
                    cst[j] = c;
                    hv[j] = go * tanhf_(c);
                }
                *reinterpret_cast<__half2*>(hn + (size_t)rEb * Hs + wpos)       = __floats2half2_rn(hv[0], hv[1]);
                *reinterpret_cast<__half2*>(hn + (size_t)(rEb + 8) * Hs + wpos) = __floats2half2_rn(hv[2], hv[3]);
            }
        }

        if (s <= Tt) grid_barrier(NBLK_REC, ++ep);
    }
}

// ---------------------------------------------------------------- final FC (physpos h)
__global__ void fc_kernel(const float* __restrict__ Wfc, const float* __restrict__ bfc,
                          float* __restrict__ out)
{
    int b = blockIdx.x;
    const __half* h = g_h1buf[1] + b * Hs;   // h1[511] written at s=513 -> parity 1
    float s = 0.f;
    for (int k = threadIdx.x; k < Hs; k += 128)
        s += __half2float(h[physpos(k)]) * Wfc[k];
    #pragma unroll
    for (int o = 16; o > 0; o >>= 1)
        s += __shfl_down_sync(0xffffffffu, s, o);
    __shared__ float sm[4];
    if ((threadIdx.x & 31) == 0) sm[threadIdx.x >> 5] = s;
    __syncthreads();
    if (threadIdx.x == 0)
        out[b] = sm[0] + sm[1] + sm[2] + sm[3] + bfc[0];
}

// ---------------------------------------------------------------- launch
extern "C" void kernel_launch(void* const* d_in, const int* in_sizes, int n_in,
                              void* d_out, int out_size)
{
    (void)in_sizes; (void)n_in; (void)out_size;
    const float* x    = (const float*)d_in[0];
    const float* Wih0 = (const float*)d_in[1];
    const float* Whh0 = (const float*)d_in[2];
    const float* b0   = (const float*)d_in[3];
    const float* Wih1 = (const float*)d_in[4];
    const float* Whh1 = (const float*)d_in[5];
    const float* b1   = (const float*)d_in[6];
    const float* Wfc  = (const float*)d_in[7];
    const float* bfc  = (const float*)d_in[8];
    float* out = (float*)d_out;

    cudaFuncSetAttribute(rec2_kernel, cudaFuncAttributeMaxDynamicSharedMemorySize, RSMEM);
    cudaFuncSetAttribute(gemm_xg_kernel, cudaFuncAttributeMaxDynamicSharedMemorySize, GSMEM);

    __half* xh  = nullptr; cudaGetSymbolAddress((void**)&xh,  g_xh);
    __half* w0h = nullptr; cudaGetSymbolAddress((void**)&w0h, g_w0h);

    tohalf_kernel<<<4096, 256>>>(x,    xh,  Bsz * Tt * Din);
    tohalf_kernel<<<1024, 256>>>(Wih0, w0h, G4 * Din);

    dim3 grid(G4 / 128, MROWS / 128);
    gemm_xg_kernel<<<grid, 256, GSMEM>>>(xh, w0h, b0, Din);
    rec2_kernel<<<NBLK_REC, RTHREADS, RSMEM>>>(Whh0, Wih1, Whh1, b1);
    fc_kernel<<<Bsz, 128>>>(Wfc, bfc, out);
}

// round 15
// speedup vs baseline: 1.3611x; 1.3611x over previous
#include <cuda_runtime.h>
#include <cuda_fp16.h>
#include <cstdint>
#include <math.h>

#define Bsz 64
#define Tt  512
#define Din 256
#define Hs  1024
#define G4  4096
#define MROWS (Tt*Bsz)
#define NBLK_REC 128
#define WSROW 1032
#define GS 3
#define GSTRIDE 40
#define STAGEH (128*GSTRIDE)
#define RTHREADS 384
#define SETH2 (64*17)           // half2 per smem partial set
// smem sets: 0,1 = grp0 ksl0/1 | 2,3 = grp1 ksl0/1 | 4,5 = grp2 ksl0/1

// persistent scratch
__device__ __half g_xgh[(size_t)MROWS * G4];     // [T][B][u*4+g] gate-INTERLEAVED layer-0 input gates
__device__ __half g_h0buf[2][Bsz * Hs];          // layer-0 hidden (physpos layout)
__device__ __half g_h1buf[2][Bsz * Hs];          // layer-1 hidden (physpos layout)
__device__ __half g_xh[(size_t)Bsz * Tt * Din];
__device__ __half g_w0h[(size_t)G4 * Din];
__device__ unsigned g_barcnt;
__device__ unsigned g_bargen;

// ---------------------------------------------------------------- helpers
__device__ __forceinline__ void mma_f16(float* d, const unsigned* a, unsigned b0, unsigned b1) {
    asm volatile(
        "mma.sync.aligned.m16n8k16.row.col.f32.f16.f16.f32 "
        "{%0,%1,%2,%3},{%4,%5,%6,%7},{%8,%9},{%0,%1,%2,%3};"
        : "+f"(d[0]), "+f"(d[1]), "+f"(d[2]), "+f"(d[3])
        : "r"(a[0]), "r"(a[1]), "r"(a[2]), "r"(a[3]), "r"(b0), "r"(b1));
}

__device__ __forceinline__ void cp16(unsigned saddr, const void* g) {
    asm volatile("cp.async.cg.shared.global [%0], [%1], 16;" :: "r"(saddr), "l"(g));
}

__device__ __forceinline__ int perm16(int c) {
    return (c < 8) ? ((c >> 1) * 4 + (c & 1)) : (((c - 8) >> 1) * 4 + 2 + (c & 1));
}
__device__ __forceinline__ int physpos(int u) {
    int blk = u >> 4;
    int o = perm16(u & 15);
    int tg = o >> 2, inner = o & 3;
    return (blk >> 1) * 32 + tg * 8 + (blk & 1) * 4 + inner;
}

__device__ __forceinline__ float sigf(float x)  { return __fdividef(1.f, 1.f + __expf(-x)); }
__device__ __forceinline__ float tanhf_(float x){ return __fdividef(2.f, 1.f + __expf(-2.f * x)) - 1.f; }

// canonical CG grid barrier: tid0 arrives + polls (acquire); exit __syncthreads
// chains cta-scope ordering to all threads. 128 pollers grid-wide (was 1536).
__device__ __forceinline__ void grid_barrier(unsigned nblk, unsigned expect) {
    __syncthreads();
    if (threadIdx.x == 0) {
        asm volatile("fence.acq_rel.gpu;" ::: "memory");
        if (atomicAdd(&g_barcnt, 1u) == nblk - 1u) {
            g_barcnt = 0;
            asm volatile("st.release.gpu.global.u32 [%0], %1;" :: "l"(&g_bargen), "r"(expect) : "memory");
        }
        unsigned cur;
        do {
            asm volatile("ld.acquire.gpu.global.u32 %0, [%1];" : "=r"(cur) : "l"(&g_bargen) : "memory");
        } while (cur < expect);
    }
    __syncthreads();
}

// ---------------------------------------------------------------- fp32 -> fp16 (+barrier reset)
__global__ void tohalf_kernel(const float* __restrict__ src, __half* __restrict__ dst, int n)
{
    if (blockIdx.x == 0 && threadIdx.x == 0) { g_barcnt = 0; g_bargen = 0; }
    for (int i = blockIdx.x * blockDim.x + threadIdx.x; i < n; i += gridDim.x * blockDim.x)
        dst[i] = __float2half_rn(src[i]);
}

// ---------------------------------------------------------------- xg0 GEMM
// epilogue remaps gate-major col c=(g*1024+u) -> u*4+g (gate-interleaved)
#define GSMEM (GS * STAGEH * 2 * 2)

__global__ __launch_bounds__(256, 2)
void gemm_xg_kernel(const __half* __restrict__ A, const __half* __restrict__ W,
                    const float* __restrict__ bias, int K)
{
    extern __shared__ __half gsm[];
    __half* As = gsm;
    __half* Bs = gsm + GS * STAGEH;

    const int tid  = threadIdx.x;
    const int lane = tid & 31, warp = tid >> 5;
    const int gid  = lane >> 2, tig = lane & 3;
    const int wm   = warp >> 1, wn = warp & 1;
    const int bm   = blockIdx.y * 128, bn = blockIdx.x * 128;

    const __half* ga[2]; const __half* gb[2]; int soff[2];
    #pragma unroll
    for (int j = 0; j < 2; ++j) {
        int i = tid + j * 256;
        int row = i >> 2, seg = (i & 3) * 8;
        int rm = bm + row;
        ga[j] = A + ((size_t)(rm & 63) * Tt + (rm >> 6)) * Din + seg;
        gb[j] = W + (size_t)(bn + row) * K + seg;
        soff[j] = row * GSTRIDE + seg;
    }
    unsigned sA = (unsigned)__cvta_generic_to_shared(As);
    unsigned sB = (unsigned)__cvta_generic_to_shared(Bs);

    const int nch = K / 32;

    auto stage = [&](int s, int k0) {
        #pragma unroll
        for (int j = 0; j < 2; ++j) {
            cp16(sA + (s * STAGEH + soff[j]) * 2, ga[j] + k0);
            cp16(sB + (s * STAGEH + soff[j]) * 2, gb[j] + k0);
        }
        asm volatile("cp.async.commit_group;");
    };

    stage(0, 0);
    stage(1, 32);

    float acc[2][8][4] = {};

    for (int c = 0; c < nch; ++c) {
        if (c + 1 < nch) asm volatile("cp.async.wait_group 1;");
        else             asm volatile("cp.async.wait_group 0;");
        __syncthreads();
        if (c + 2 < nch) stage((c + 2) % GS, (c + 2) * 32);

        const __half* Asl = As + (c % GS) * STAGEH;
        const __half* Bsl = Bs + (c % GS) * STAGEH;
        #pragma unroll
        for (int s = 0; s < 2; ++s) {
            int kk = s * 16;
            unsigned a[2][4];
            #pragma unroll
            for (int mt = 0; mt < 2; ++mt) {
                int m = wm * 32 + mt * 16 + gid;
                a[mt][0] = *(const unsigned*)&Asl[m * GSTRIDE + kk + 2 * tig];
                a[mt][1] = *(const unsigned*)&Asl[(m + 8) * GSTRIDE + kk + 2 * tig];
                a[mt][2] = *(const unsigned*)&Asl[m * GSTRIDE + kk + 8 + 2 * tig];
                a[mt][3] = *(const unsigned*)&Asl[(m + 8) * GSTRIDE + kk + 8 + 2 * tig];
            }
            #pragma unroll
            for (int nt = 0; nt < 8; ++nt) {
                int n = wn * 64 + nt * 8 + gid;
                unsigned b0 = *(const unsigned*)&Bsl[n * GSTRIDE + kk + 2 * tig];
                unsigned b1 = *(const unsigned*)&Bsl[n * GSTRIDE + kk + 8 + 2 * tig];
                mma_f16(acc[0][nt], a[0], b0, b1);
                mma_f16(acc[1][nt], a[1], b0, b1);
            }
        }
    }

    #pragma unroll
    for (int mt = 0; mt < 2; ++mt) {
        #pragma unroll
        for (int nt = 0; nt < 8; ++nt) {
            int row = bm + wm * 32 + mt * 16 + gid;
            int col = bn + wn * 64 + nt * 8 + 2 * tig;
            float bc0 = bias[col], bc1 = bias[col + 1];
            int rm0 = (col & 1023) * 4 + (col >> 10);
            int rm1 = ((col + 1) & 1023) * 4 + ((col + 1) >> 10);
            g_xgh[(size_t)row * G4 + rm0] = __float2half_rn(acc[mt][nt][0] + bc0);
            g_xgh[(size_t)row * G4 + rm1] = __float2half_rn(acc[mt][nt][1] + bc1);
            g_xgh[(size_t)(row + 8) * G4 + rm0] = __float2half_rn(acc[mt][nt][2] + bc0);
            g_xgh[(size_t)(row + 8) * G4 + rm1] = __float2half_rn(acc[mt][nt][3] + bc1);
        }
    }
}

// ---------------------------------------------------------------- fused 2-layer recurrence
// r13 structure: 384 threads = 3 groups x (2 K-slices x 2 M-slices), m32n32k512 warp tiles.
// fp16 partial exchange in smem; bar 1 = grp0 (128 thr), bar 2 = grp1+grp2 (256 thr).
#define RSMEM (96*WSROW*2 + 6*SETH2*4)

__global__ __launch_bounds__(RTHREADS, 1)
void rec2_kernel(const float* __restrict__ Whh0, const float* __restrict__ Wih1,
                 const float* __restrict__ Whh1, const float* __restrict__ b1)
{
    extern __shared__ unsigned char smraw[];
    __half*  Ws   = (__half*)smraw;                        // [3][32][WSROW]
    __half2* scr2 = (__half2*)(smraw + 96 * WSROW * 2);    // [6][64][17]

    const int tid  = threadIdx.x;
    const int lane = tid & 31, warp = tid >> 5;
    const int gid  = lane >> 2, tig = lane & 3;
    const int grp  = warp >> 2;            // 0:Whh0 1:Wih1 2:Whh1
    const int w4   = warp & 3;
    const int ksl  = w4 >> 1, ms = w4 & 1;
    const int u0   = blockIdx.x * 8;
    const int r0   = ms * 32 + gid;

    // one-time: 3 weight slices -> smem fp16
    {
        const float* srcs[3] = {Whh0, Wih1, Whh1};
        for (int sl = 0; sl < 3; ++sl) {
            const float* src = srcs[sl];
            __half* dst = Ws + sl * 32 * WSROW;
            for (int i = tid; i < 32 * Hs; i += RTHREADS) {
                int l = i >> 10, k = i & 1023;
                int g = l >> 3, n = l & 7;
                dst[l * WSROW + k] = __float2half_rn(src[(size_t)(g * Hs + u0 + n) * Hs + k]);
            }
        }
    }
    // zero h "minus-one" buffers: h0[-1] parity 1; h1[-1] parity 0
    for (int i = tid; i < 512; i += RTHREADS) {
        int b = i >> 3, uu = i & 7;
        int col = physpos(u0 + uu);
        g_h0buf[1][b * Hs + col] = __float2half_rn(0.f);
        g_h1buf[0][b * Hs + col] = __float2half_rn(0.f);
    }

    // ldmatrix lane pointers, K-slice baked in
    const int ltile = lane >> 3, lrow = lane & 7;
    unsigned lp0, lp1;
    {
        const __half* wsl = Ws + grp * 32 * WSROW + ksl * 512;
        const __half* p0 = wsl + (size_t)(((ltile >> 1)) * 8 + lrow) * WSROW + (ltile & 1) * 8;
        const __half* p1 = wsl + (size_t)((2 + (ltile >> 1)) * 8 + lrow) * WSROW + (ltile & 1) * 8;
        lp0 = (unsigned)__cvta_generic_to_shared(p0);
        lp1 = (unsigned)__cvta_generic_to_shared(p1);
    }

    const int rE = w4 * 16 + gid;
    float cst[4] = {0.f, 0.f, 0.f, 0.f};
    float bi1[4][2];
    if (grp == 2) {
        #pragma unroll
        for (int g = 0; g < 4; ++g) {
            bi1[g][0] = b1[g * Hs + u0 + 2 * tig];
            bi1[g][1] = b1[g * Hs + u0 + 2 * tig + 1];
        }
    }
    const int wpos = physpos(u0 + 2 * tig);

    unsigned ep = 0;
    grid_barrier(NBLK_REC, ++ep);

    for (int s = 0; s <= Tt; ++s) {
        // packed xg prefetch: 2 x LDG.128 (gate-interleaved layout)
        uint4 pxA, pxB;
        if (grp == 0 && s < Tt) {
            const __half* xb = g_xgh + ((size_t)s * Bsz) * G4 + 4 * (u0 + 2 * tig);
            pxA = *(const uint4*)(xb + (size_t)rE * G4);
            pxB = *(const uint4*)(xb + (size_t)(rE + 8) * G4);
        }

        const bool doM = (grp == 0) ? (s < Tt) : (s >= 1);
        float acc[4][2][4] = {};    // [gate][mtile][frag]

        if (doM) {
            const __half* hp = (grp == 2) ? g_h1buf[(s + 1) & 1] : g_h0buf[(s + 1) & 1];
            const uint4* aP0 = (const uint4*)(hp + (size_t)(r0)      * Hs + ksl * 512) + tig;
            const uint4* aP1 = (const uint4*)(hp + (size_t)(r0 + 8)  * Hs + ksl * 512) + tig;
            const uint4* aP2 = (const uint4*)(hp + (size_t)(r0 + 16) * Hs + ksl * 512) + tig;
            const uint4* aP3 = (const uint4*)(hp + (size_t)(r0 + 24) * Hs + ksl * 512) + tig;
            #pragma unroll 8
            for (int j = 0; j < 16; ++j) {
                uint4 v0 = aP0[4 * j], v1 = aP1[4 * j], v2 = aP2[4 * j], v3 = aP3[4 * j];
                unsigned b0, b1r, b2, b3;
                {   // kstep 2j
                    unsigned a0[4] = {v0.x, v1.x, v0.y, v1.y};
                    unsigned a1[4] = {v2.x, v3.x, v2.y, v3.y};
                    asm volatile("ldmatrix.sync.aligned.m8n8.x4.shared.b16 {%0,%1,%2,%3}, [%4];"
                                 : "=r"(b0), "=r"(b1r), "=r"(b2), "=r"(b3) : "r"(lp0 + j * 64));
                    mma_f16(acc[0][0], a0, b0, b1r); mma_f16(acc[0][1], a1, b0, b1r);
                    mma_f16(acc[1][0], a0, b2, b3);  mma_f16(acc[1][1], a1, b2, b3);
                    asm volatile("ldmatrix.sync.aligned.m8n8.x4.shared.b16 {%0,%1,%2,%3}, [%4];"
                                 : "=r"(b0), "=r"(b1r), "=r"(b2), "=r"(b3) : "r"(lp1 + j * 64));
                    mma_f16(acc[2][0], a0, b0, b1r); mma_f16(acc[2][1], a1, b0, b1r);
                    mma_f16(acc[3][0], a0, b2, b3);  mma_f16(acc[3][1], a1, b2, b3);
                }
                {   // kstep 2j+1
                    unsigned a0[4] = {v0.z, v1.z, v0.w, v1.w};
                    unsigned a1[4] = {v2.z, v3.z, v2.w, v3.w};
                    asm volatile("ldmatrix.sync.aligned.m8n8.x4.shared.b16 {%0,%1,%2,%3}, [%4];"
                                 : "=r"(b0), "=r"(b1r), "=r"(b2), "=r"(b3) : "r"(lp0 + j * 64 + 32));
                    mma_f16(acc[0][0], a0, b0, b1r); mma_f16(acc[0][1], a1, b0, b1r);
                    mma_f16(acc[1][0], a0, b2, b3);  mma_f16(acc[1][1], a1, b2, b3);
                    asm volatile("ldmatrix.sync.aligned.m8n8.x4.shared.b16 {%0,%1,%2,%3}, [%4];"
                                 : "=r"(b0), "=r"(b1r), "=r"(b2), "=r"(b3) : "r"(lp1 + j * 64 + 32));
                    mma_f16(acc[2][0], a0, b0, b1r); mma_f16(acc[2][1], a1, b0, b1r);
                    mma_f16(acc[3][0], a0, b2, b3);  mma_f16(acc[3][1], a1, b2, b3);
                }
            }
            // store fp16 partials: set = grp*2 + ksl
            __half2* sc = scr2 + (grp * 2 + ksl) * SETH2;
            #pragma unroll
            for (int g = 0; g < 4; ++g) {
                #pragma unroll
                for (int mt = 0; mt < 2; ++mt) {
                    int row = r0 + mt * 16;
                    sc[row * 17 + g * 4 + tig]       = __floats2half2_rn(acc[g][mt][0], acc[g][mt][1]);
                    sc[(row + 8) * 17 + g * 4 + tig] = __floats2half2_rn(acc[g][mt][2], acc[g][mt][3]);
                }
            }
        }

        if (grp == 0) {
            if (s < Tt) {
                asm volatile("bar.sync 1, 128;" ::: "memory");
                const __half2* s0 = scr2;
                const __half2* s1 = scr2 + SETH2;
                float2 G[4][2];
                #pragma unroll
                for (int g = 0; g < 4; ++g) {
                    #pragma unroll
                    for (int fr = 0; fr < 2; ++fr) {
                        int r = rE + fr * 8;
                        __half2 pa = s0[r * 17 + g * 4 + tig];
                        __half2 pb = s1[r * 17 + g * 4 + tig];
                        G[g][fr] = make_float2(__low2float(pa) + __low2float(pb),
                                               __high2float(pa) + __high2float(pb));
                    }
                }
                __half* hn = g_h0buf[s & 1];
                float hv[4];
                #pragma unroll
                for (int j = 0; j < 4; ++j) {
                    int fr = j >> 1, fc = j & 1;
                    const uint4& P = fr ? pxB : pxA;
                    unsigned plo = fc ? P.z : P.x;     // (i,f)
                    unsigned phi = fc ? P.w : P.y;     // (g,o)
                    __half2 vlo = *reinterpret_cast<__half2*>(&plo);
                    __half2 vhi = *reinterpret_cast<__half2*>(&phi);
                    float gi = (fc ? G[0][fr].y : G[0][fr].x) + __low2float(vlo);
                    float gf = (fc ? G[1][fr].y : G[1][fr].x) + __high2float(vlo);
                    float gg = (fc ? G[2][fr].y : G[2][fr].x) + __low2float(vhi);
                    float go = (fc ? G[3][fr].y : G[3][fr].x) + __high2float(vhi);
                    gi = sigf(gi); gf = sigf(gf); gg = tanhf_(gg); go = sigf(go);
                    float c = gf * cst[j] + gi * gg;
                    cst[j] = c;
                    hv[j] = go * tanhf_(c);
                }
                *reinterpret_cast<__half2*>(hn + (size_t)rE * Hs + wpos)       = __floats2half2_rn(hv[0], hv[1]);
                *reinterpret_cast<__half2*>(hn + (size_t)(rE + 8) * Hs + wpos) = __floats2half2_rn(hv[2], hv[3]);
            }
        } else {
            if (s >= 1) {
                asm volatile("bar.sync 2, 256;" ::: "memory");
                if (grp == 2) {
                    const __half2* q0 = scr2 + 2 * SETH2;   // grp1 ksl0
                    const __half2* q1 = scr2 + 3 * SETH2;   // grp1 ksl1
                    const __half2* s0 = scr2 + 4 * SETH2;   // own ksl0
                    const __half2* s1 = scr2 + 5 * SETH2;   // own ksl1
                    float2 G[4][2];
                    #pragma unroll
                    for (int g = 0; g < 4; ++g) {
                        #pragma unroll
                        for (int fr = 0; fr < 2; ++fr) {
                            int r = rE + fr * 8;
                            int idx = r * 17 + g * 4 + tig;
                            __half2 a = q0[idx], b = q1[idx], c = s0[idx], d = s1[idx];
                            G[g][fr] = make_float2(
                                __low2float(a) + __low2float(b) + __low2float(c) + __low2float(d),
                                __high2float(a) + __high2float(b) + __high2float(c) + __high2float(d));
                        }
                    }
                    __half* hn = g_h1buf[s & 1];     // h1[s-1]
                    float hv[4];
                    #pragma unroll
                    for (int j = 0; j < 4; ++j) {
                        int fr = j >> 1, fc = j & 1;
                        float gi = (fc ? G[0][fr].y : G[0][fr].x) + bi1[0][fc];
                        float gf = (fc ? G[1][fr].y : G[1][fr].x) + bi1[1][fc];
                        float gg = (fc ? G[2][fr].y : G[2][fr].x) + bi1[2][fc];
                        float go = (fc ? G[3][fr].y : G[3][fr].x) + bi1[3][fc];
                        gi = sigf(gi); gf = sigf(gf); gg = tanhf_(gg); go = sigf(go);
                        float c = gf * cst[j] + gi * gg;
                        cst[j] = c;
                        hv[j] = go * tanhf_(c);
                    }
                    *reinterpret_cast<__half2*>(hn + (size_t)rE * Hs + wpos)       = __floats2half2_rn(hv[0], hv[1]);
                    *reinterpret_cast<__half2*>(hn + (size_t)(rE + 8) * Hs + wpos) = __floats2half2_rn(hv[2], hv[3]);
                }
            }
        }

        if (s < Tt) grid_barrier(NBLK_REC, ++ep);
    }
}

// ---------------------------------------------------------------- final FC (physpos h)
__global__ void fc_kernel(const float* __restrict__ Wfc, const float* __restrict__ bfc,
                          float* __restrict__ out)
{
    int b = blockIdx.x;
    const __half* h = g_h1buf[0] + b * Hs;   // h1[511] written at s=512 -> parity 0
    float s = 0.f;
    for (int k = threadIdx.x; k < Hs; k += 128)
        s += __half2float(h[physpos(k)]) * Wfc[k];
    #pragma unroll
    for (int o = 16; o > 0; o >>= 1)
        s += __shfl_down_sync(0xffffffffu, s, o);
    __shared__ float sm[4];
    if ((threadIdx.x & 31) == 0) sm[threadIdx.x >> 5] = s;
    __syncthreads();
    if (threadIdx.x == 0)
        out[b] = sm[0] + sm[1] + sm[2] + sm[3] + bfc[0];
}

// ---------------------------------------------------------------- launch
extern "C" void kernel_launch(void* const* d_in, const int* in_sizes, int n_in,
                              void* d_out, int out_size)
{
    (void)in_sizes; (void)n_in; (void)out_size;
    const float* x    = (const float*)d_in[0];
    const float* Wih0 = (const float*)d_in[1];
    const float* Whh0 = (const float*)d_in[2];
    const float* b0   = (const float*)d_in[3];
    const float* Wih1 = (const float*)d_in[4];
    const float* Whh1 = (const float*)d_in[5];
    const float* b1   = (const float*)d_in[6];
    const float* Wfc  = (const float*)d_in[7];
    const float* bfc  = (const float*)d_in[8];
    float* out = (float*)d_out;

    cudaFuncSetAttribute(rec2_kernel, cudaFuncAttributeMaxDynamicSharedMemorySize, RSMEM);
    cudaFuncSetAttribute(gemm_xg_kernel, cudaFuncAttributeMaxDynamicSharedMemorySize, GSMEM);

    __half* xh  = nullptr; cudaGetSymbolAddress((void**)&xh,  g_xh);
    __half* w0h = nullptr; cudaGetSymbolAddress((void**)&w0h, g_w0h);

    tohalf_kernel<<<4096, 256>>>(x,    xh,  Bsz * Tt * Din);
    tohalf_kernel<<<1024, 256>>>(Wih0, w0h, G4 * Din);

    dim3 grid(G4 / 128, MROWS / 128);
    gemm_xg_kernel<<<grid, 256, GSMEM>>>(xh, w0h, b0, Din);
    rec2_kernel<<<NBLK_REC, RTHREADS, RSMEM>>>(Whh0, Wih1, Whh1, b1);
    fc_kernel<<<Bsz, 128>>>(Wfc, bfc, out);
}